// round 11
// baseline (speedup 1.0000x reference)
#include <cuda_runtime.h>
#include <math.h>

#define BATCH 256
#define SEQ   512
#define VOCAB 50000
#define EMB   128
#define UNIT  512
#define HSZ   (BATCH*UNIT)   // one hidden-state matrix

// Scratch (static device arrays: allocation-free per harness rules)
__device__ __align__(16) float g_emb2[(size_t)VOCAB * UNIT]; // emb @ Wx0 + b0  (~102 MB)
__device__ __align__(16) float g_h[6 * HSZ];                 // [layer*2 + parity][B][U]

typedef unsigned long long u64;

__device__ __forceinline__ void fma2(u64& d, u64 a, u64 b) {
    asm("fma.rn.f32x2 %0, %1, %2, %0;" : "+l"(d) : "l"(a), "l"(b));
}
__device__ __forceinline__ u64 bcast2(float x) {
    u64 r; asm("mov.b64 %0, {%1, %1};" : "=l"(r) : "f"(x)); return r;
}
__device__ __forceinline__ float2 unpack2(u64 v) {
    float2 r; asm("mov.b64 {%0, %1}, %2;" : "=f"(r.x), "=f"(r.y) : "l"(v)); return r;
}

// 16-k-step inner product on the 4x8 microtile (16 f32x2 accumulators)
#define COMPUTE_TILE() do {                                                              \
    _Pragma("unroll")                                                                    \
    for (int k5 = 0; k5 < 16; k5++) {                                                    \
        float4 a = *(const float4*)&As[k5][tm * 4];                                      \
        const ulonglong2* bp = (const ulonglong2*)&Bs[k5][tn * 8];                       \
        ulonglong2 bA = bp[0]; ulonglong2 bB = bp[1];                                    \
        u64 aa;                                                                          \
        aa = bcast2(a.x); fma2(acc[0][0],aa,bA.x); fma2(acc[0][1],aa,bA.y);              \
                          fma2(acc[0][2],aa,bB.x); fma2(acc[0][3],aa,bB.y);              \
        aa = bcast2(a.y); fma2(acc[1][0],aa,bA.x); fma2(acc[1][1],aa,bA.y);              \
                          fma2(acc[1][2],aa,bB.x); fma2(acc[1][3],aa,bB.y);              \
        aa = bcast2(a.z); fma2(acc[2][0],aa,bA.x); fma2(acc[2][1],aa,bA.y);              \
                          fma2(acc[2][2],aa,bB.x); fma2(acc[2][3],aa,bB.y);              \
        aa = bcast2(a.w); fma2(acc[3][0],aa,bA.x); fma2(acc[3][1],aa,bA.y);              \
                          fma2(acc[3][2],aa,bB.x); fma2(acc[3][3],aa,bB.y);              \
    } } while (0)

// ---------------------------------------------------------------------------
// Zero the 6 hidden-state buffers (must be zero at the start of EVERY launch)
// ---------------------------------------------------------------------------
__global__ void zero_h_kernel() {
    int i = blockIdx.x * 256 + threadIdx.x;      // 768*256 = 196608 float4 = 6*HSZ floats
    ((float4*)g_h)[i] = make_float4(0.f, 0.f, 0.f, 0.f);
}

// ---------------------------------------------------------------------------
// emb2[v][n] = sum_k emb[v][k] * Wx0[k][n] + b0[n]     (M=50000, N=512, K=128)
// ---------------------------------------------------------------------------
__global__ __launch_bounds__(128) void emb2_kernel(
    const float* __restrict__ emb, const float* __restrict__ Wx0,
    const float* __restrict__ b0)
{
    __shared__ __align__(16) float As[16][68];
    __shared__ __align__(16) float Bs[16][64];
    int tid = threadIdx.x;
    int n0 = blockIdx.x * 64;
    int m0 = blockIdx.y * 64;
    int tm = tid >> 3, tn = tid & 7;

    u64 acc[4][4];
#pragma unroll
    for (int i = 0; i < 4; i++)
#pragma unroll
        for (int j = 0; j < 4; j++) acc[i][j] = 0ull;

    float4 ra[2], rb[2];
    auto ld = [&](int kb) {
#pragma unroll
        for (int it = 0; it < 2; it++) {
            int idx = tid + it * 128;
            int m = idx >> 2, kg = idx & 3;
            int row = m0 + m;
            if (row < VOCAB)
                ra[it] = *(const float4*)&emb[(size_t)row * EMB + kb * 16 + kg * 4];
            else
                ra[it] = make_float4(0.f, 0.f, 0.f, 0.f);
            int kk = idx >> 4, ng = idx & 15;
            rb[it] = *(const float4*)&Wx0[(size_t)(kb * 16 + kk) * UNIT + n0 + ng * 4];
        }
    };

    ld(0);
    for (int kb = 0; kb < 8; kb++) {                 // K = 128 = 8 * 16
#pragma unroll
        for (int it = 0; it < 2; it++) {
            int idx = tid + it * 128;
            int m = idx >> 2, kg = idx & 3;
            As[kg * 4 + 0][m] = ra[it].x; As[kg * 4 + 1][m] = ra[it].y;
            As[kg * 4 + 2][m] = ra[it].z; As[kg * 4 + 3][m] = ra[it].w;
            int kk = idx >> 4, ng = idx & 15;
            *(float4*)&Bs[kk][ng * 4] = rb[it];
        }
        __syncthreads();
        if (kb + 1 < 8) ld(kb + 1);
        COMPUTE_TILE();
        __syncthreads();
    }

#pragma unroll
    for (int i = 0; i < 4; i++) {
        int row = m0 + tm * 4 + i;
        if (row >= VOCAB) break;
        float* po = g_emb2 + (size_t)row * UNIT + n0 + tn * 8;
        const float* bb = b0 + n0 + tn * 8;
#pragma unroll
        for (int j = 0; j < 4; j++) {
            float2 v = unpack2(acc[i][j]);
            ((float2*)po)[j] = make_float2(v.x + bb[j * 2], v.y + bb[j * 2 + 1]);
        }
    }
}

// ---------------------------------------------------------------------------
// One wavefront tick: layer0@t, layer1@t-1, layer2@t-2 fused GEMM + tanh.
// Grid (8, 12): blockIdx.y/4 = layer, (blockIdx.y&3)*64 = batch-tile origin.
// ---------------------------------------------------------------------------
__global__ __launch_bounds__(128) void tick_kernel(
    int t,
    const float* __restrict__ Wh0, const float* __restrict__ Wx1,
    const float* __restrict__ Wh1, const float* __restrict__ b1,
    const int* __restrict__ tokens)
{
    int layer = blockIdx.y >> 2;
    if (layer == 0 && t >= SEQ) return;              // h0(t) only for t in [0,512)
    if (layer == 1 && (t < 1 || t > SEQ)) return;    // h1(t-1) for t in [1,512]
    if (layer == 2 && t < 2) return;                 // h2(t-2) for t in [2,513]

    int p = t & 1, q = p ^ 1;
    const float *Alo, *Ahi, *Blo, *Bhi;
    float* out;
    int nkb;
    if (layer == 0) {        // h0' = tanh(h0_old @ Wh0 + emb2[tok])         K=512
        Alo = g_h + q * HSZ;       Ahi = Alo;
        Blo = Wh0;                 Bhi = Wh0;
        out = g_h + p * HSZ;       nkb = 32;
    } else if (layer == 1) { // h1' = tanh(h0_old @ Wx1 + h1_old @ Wh1 + b1) K=1024
        Alo = g_h + q * HSZ;       Ahi = g_h + (2 + q) * HSZ;
        Blo = Wx1;                 Bhi = Wh1;
        out = g_h + (2 + p) * HSZ; nkb = 64;
    } else {                 // h2' = tanh(h1_old @ Wx1 + h2_old @ Wh1 + b1) K=1024
        Alo = g_h + (2 + q) * HSZ; Ahi = g_h + (4 + q) * HSZ;
        Blo = Wx1;                 Bhi = Wh1;
        out = g_h + (4 + p) * HSZ; nkb = 64;
    }

    __shared__ __align__(16) float As[16][68];
    __shared__ __align__(16) float Bs[16][64];
    int tid = threadIdx.x;
    int n0 = blockIdx.x * 64;
    int m0 = (blockIdx.y & 3) * 64;
    int tm = tid >> 3, tn = tid & 7;

    u64 acc[4][4];
#pragma unroll
    for (int i = 0; i < 4; i++)
#pragma unroll
        for (int j = 0; j < 4; j++) acc[i][j] = 0ull;

    float4 ra[2], rb[2];
    auto ld = [&](int kb) {
        const float* A = (kb < 32) ? Alo : Ahi;
        const float* B = (kb < 32) ? Blo : Bhi;
        int kc = (kb * 16) & 511;
#pragma unroll
        for (int it = 0; it < 2; it++) {
            int idx = tid + it * 128;
            int m = idx >> 2, kg = idx & 3;
            ra[it] = *(const float4*)&A[(size_t)(m0 + m) * UNIT + kc + kg * 4];
            int kk = idx >> 4, ng = idx & 15;
            rb[it] = *(const float4*)&B[(size_t)(kc + kk) * UNIT + n0 + ng * 4];
        }
    };

    ld(0);
    for (int kb = 0; kb < nkb; kb++) {
#pragma unroll
        for (int it = 0; it < 2; it++) {
            int idx = tid + it * 128;
            int m = idx >> 2, kg = idx & 3;
            As[kg * 4 + 0][m] = ra[it].x; As[kg * 4 + 1][m] = ra[it].y;
            As[kg * 4 + 2][m] = ra[it].z; As[kg * 4 + 3][m] = ra[it].w;
            int kk = idx >> 4, ng = idx & 15;
            *(float4*)&Bs[kk][ng * 4] = rb[it];
        }
        __syncthreads();
        if (kb + 1 < nkb) ld(kb + 1);
        COMPUTE_TILE();
        __syncthreads();
    }

    // Epilogue: + (emb2 gather | bias), tanh, store
#pragma unroll
    for (int i = 0; i < 4; i++) {
        int m = m0 + tm * 4 + i;                 // batch index
        float add[8];
        if (layer == 0) {
            int tok = tokens[m * SEQ + t];
            const float* e = g_emb2 + (size_t)tok * UNIT + n0 + tn * 8;
#pragma unroll
            for (int c = 0; c < 8; c++) add[c] = e[c];
        } else {
            const float* bb = b1 + n0 + tn * 8;
#pragma unroll
            for (int c = 0; c < 8; c++) add[c] = bb[c];
        }
        float* po = out + (size_t)m * UNIT + n0 + tn * 8;
#pragma unroll
        for (int j = 0; j < 4; j++) {
            float2 v = unpack2(acc[i][j]);
            ((float2*)po)[j] = make_float2(tanhf(v.x + add[j * 2]),
                                           tanhf(v.y + add[j * 2 + 1]));
        }
    }
}

// ---------------------------------------------------------------------------
// out[b] = sigmoid(h2_final[b] . fc_w + fc_b)   ; h2_final lives at parity 1
// ---------------------------------------------------------------------------
__global__ void final_kernel(const float* __restrict__ fc_w,
                             const float* __restrict__ fc_b,
                             float* __restrict__ out)
{
    int b = blockIdx.x;
    int lane = threadIdx.x;
    const float* h = g_h + 5 * HSZ + (size_t)b * UNIT;  // layer2, parity (513&1)=1
    float s = 0.f;
    for (int k = lane; k < UNIT; k += 32) s += h[k] * fc_w[k];
#pragma unroll
    for (int o = 16; o; o >>= 1) s += __shfl_xor_sync(0xffffffffu, s, o);
    if (lane == 0) out[b] = 1.f / (1.f + expf(-(s + fc_b[0])));
}

// ---------------------------------------------------------------------------
extern "C" void kernel_launch(void* const* d_in, const int* in_sizes, int n_in,
                              void* d_out, int out_size)
{
    const int*   tokens = (const int*)  d_in[0];
    const float* emb    = (const float*)d_in[1];
    const float* Wx0    = (const float*)d_in[2];
    const float* Wh0    = (const float*)d_in[3];
    const float* b0     = (const float*)d_in[4];
    const float* Wx1    = (const float*)d_in[5];
    const float* Wh1    = (const float*)d_in[6];
    const float* b1     = (const float*)d_in[7];
    const float* fc_w   = (const float*)d_in[8];
    const float* fc_b   = (const float*)d_in[9];
    float* out = (float*)d_out;

    // 1. Zero hidden-state buffers (required every launch: graph replays reuse them)
    zero_h_kernel<<<768, 256>>>();

    // 2. emb2 = emb @ Wx0 + b0   (one-shot, fully parallel)
    emb2_kernel<<<dim3(8, (VOCAB + 63) / 64), 128>>>(emb, Wx0, b0);

    // 3. Wavefront over 514 ticks: layer0@t, layer1@t-1, layer2@t-2 per tick
    for (int t = 0; t < SEQ + 2; t++)
        tick_kernel<<<dim3(8, 12), 128>>>(t, Wh0, Wx1, Wh1, b1, tokens);

    // 4. logits -> sigmoid
    final_kernel<<<BATCH, 32>>>(fc_w, fc_b, out);
}

// round 12
// speedup vs baseline: 1.1109x; 1.1109x over previous
#include <cuda_runtime.h>
#include <math.h>

#define BATCH 256
#define SEQ   512
#define VOCAB 50000
#define EMB   128
#define UNIT  512
#define HSZ   (BATCH*UNIT)   // one hidden-state matrix
#define KB    32             // k-rows staged per iteration in tick kernel

// Scratch (static device arrays: allocation-free per harness rules)
__device__ __align__(16) float g_emb2[(size_t)VOCAB * UNIT]; // emb @ Wx0 + b0  (~102 MB)
__device__ __align__(16) float g_h[6 * HSZ];                 // [layer*2 + parity][B][U]

typedef unsigned long long u64;

__device__ __forceinline__ void fma2(u64& d, u64 a, u64 b) {
    asm("fma.rn.f32x2 %0, %1, %2, %0;" : "+l"(d) : "l"(a), "l"(b));
}
__device__ __forceinline__ void add2(u64& d, u64 a) {
    asm("add.rn.f32x2 %0, %0, %1;" : "+l"(d) : "l"(a));
}
__device__ __forceinline__ u64 bcast2(float x) {
    u64 r; asm("mov.b64 %0, {%1, %1};" : "=l"(r) : "f"(x)); return r;
}
__device__ __forceinline__ float2 unpack2(u64 v) {
    float2 r; asm("mov.b64 {%0, %1}, %2;" : "=f"(r.x), "=f"(r.y) : "l"(v)); return r;
}

// ---------------------------------------------------------------------------
// Zero the 6 hidden-state buffers (must be zero at the start of EVERY launch)
// ---------------------------------------------------------------------------
__global__ void zero_h_kernel() {
    int i = blockIdx.x * 256 + threadIdx.x;      // 768*256 float4 = 6*HSZ floats
    ((float4*)g_h)[i] = make_float4(0.f, 0.f, 0.f, 0.f);
}

// ---------------------------------------------------------------------------
// emb2[v][n] = sum_k emb[v][k] * Wx0[k][n] + b0[n]     (M=50000, N=512, K=128)
// (one-shot, fully parallel, ~2% of runtime: unchanged from R10)
// ---------------------------------------------------------------------------
__global__ __launch_bounds__(128) void emb2_kernel(
    const float* __restrict__ emb, const float* __restrict__ Wx0,
    const float* __restrict__ b0)
{
    __shared__ __align__(16) float As[16][68];
    __shared__ __align__(16) float Bs[16][64];
    int tid = threadIdx.x;
    int n0 = blockIdx.x * 64;
    int m0 = blockIdx.y * 64;
    int tm = tid >> 3, tn = tid & 7;

    u64 acc[4][4];
#pragma unroll
    for (int i = 0; i < 4; i++)
#pragma unroll
        for (int j = 0; j < 4; j++) acc[i][j] = 0ull;

    float4 ra[2], rb[2];
    auto ld = [&](int kb) {
#pragma unroll
        for (int it = 0; it < 2; it++) {
            int idx = tid + it * 128;
            int m = idx >> 2, kg = idx & 3;
            int row = m0 + m;
            if (row < VOCAB)
                ra[it] = *(const float4*)&emb[(size_t)row * EMB + kb * 16 + kg * 4];
            else
                ra[it] = make_float4(0.f, 0.f, 0.f, 0.f);
            int kk = idx >> 4, ng = idx & 15;
            rb[it] = *(const float4*)&Wx0[(size_t)(kb * 16 + kk) * UNIT + n0 + ng * 4];
        }
    };

    ld(0);
    for (int kb = 0; kb < 8; kb++) {                 // K = 128 = 8 * 16
#pragma unroll
        for (int it = 0; it < 2; it++) {
            int idx = tid + it * 128;
            int m = idx >> 2, kg = idx & 3;
            As[kg * 4 + 0][m] = ra[it].x; As[kg * 4 + 1][m] = ra[it].y;
            As[kg * 4 + 2][m] = ra[it].z; As[kg * 4 + 3][m] = ra[it].w;
            int kk = idx >> 4, ng = idx & 15;
            *(float4*)&Bs[kk][ng * 4] = rb[it];
        }
        __syncthreads();
        if (kb + 1 < 8) ld(kb + 1);
#pragma unroll
        for (int k5 = 0; k5 < 16; k5++) {
            float4 a = *(const float4*)&As[k5][tm * 4];
            const ulonglong2* bp = (const ulonglong2*)&Bs[k5][tn * 8];
            ulonglong2 bA = bp[0]; ulonglong2 bB = bp[1];
            u64 aa;
            aa = bcast2(a.x); fma2(acc[0][0],aa,bA.x); fma2(acc[0][1],aa,bA.y);
                              fma2(acc[0][2],aa,bB.x); fma2(acc[0][3],aa,bB.y);
            aa = bcast2(a.y); fma2(acc[1][0],aa,bA.x); fma2(acc[1][1],aa,bA.y);
                              fma2(acc[1][2],aa,bB.x); fma2(acc[1][3],aa,bB.y);
            aa = bcast2(a.z); fma2(acc[2][0],aa,bA.x); fma2(acc[2][1],aa,bA.y);
                              fma2(acc[2][2],aa,bB.x); fma2(acc[2][3],aa,bB.y);
            aa = bcast2(a.w); fma2(acc[3][0],aa,bA.x); fma2(acc[3][1],aa,bA.y);
                              fma2(acc[3][2],aa,bB.x); fma2(acc[3][3],aa,bB.y);
        }
        __syncthreads();
    }

#pragma unroll
    for (int i = 0; i < 4; i++) {
        int row = m0 + tm * 4 + i;
        if (row >= VOCAB) break;
        float* po = g_emb2 + (size_t)row * UNIT + n0 + tn * 8;
        const float* bb = b0 + n0 + tn * 8;
#pragma unroll
        for (int j = 0; j < 4; j++) {
            float2 v = unpack2(acc[i][j]);
            ((float2*)po)[j] = make_float2(v.x + bb[j * 2], v.y + bb[j * 2 + 1]);
        }
    }
}

// ---------------------------------------------------------------------------
// One wavefront tick: layer0@t, layer1@t-1, layer2@t-2 fused GEMM + tanh.
// v2: 256 threads, in-block K-split (warps 0-3 vs 4-7) for 2 warps/SMSP,
//     double-buffered 32-k SMEM stages (one __syncthreads per stage),
//     SMEM f32x2 reduction of the two K-partials before the tanh epilogue.
// Grid (8, 12): blockIdx.y/4 = layer, (blockIdx.y&3)*64 = batch-tile origin.
// ---------------------------------------------------------------------------
__global__ __launch_bounds__(256) void tick_kernel(
    int t,
    const float* __restrict__ Wh0, const float* __restrict__ Wx1,
    const float* __restrict__ Wh1, const float* __restrict__ b1,
    const int* __restrict__ tokens)
{
    int layer = blockIdx.y >> 2;
    if (layer == 0 && t >= SEQ) return;              // h0(t) only for t in [0,512)
    if (layer == 1 && (t < 1 || t > SEQ)) return;    // h1(t-1) for t in [1,512]
    if (layer == 2 && t < 2) return;                 // h2(t-2) for t in [2,513]

    int p = t & 1, q = p ^ 1;
    const float *Alo, *Ahi, *Blo, *Bhi;
    float* out;
    int nst;                                         // number of 32-k stages
    if (layer == 0) {        // h0' = tanh(h0_old @ Wh0 + emb2[tok])         K=512
        Alo = g_h + q * HSZ;       Ahi = Alo;
        Blo = Wh0;                 Bhi = Wh0;
        out = g_h + p * HSZ;       nst = 16;
    } else if (layer == 1) { // h1' = tanh(h0_old @ Wx1 + h1_old @ Wh1 + b1) K=1024
        Alo = g_h + q * HSZ;       Ahi = g_h + (2 + q) * HSZ;
        Blo = Wx1;                 Bhi = Wh1;
        out = g_h + (2 + p) * HSZ; nst = 32;
    } else {                 // h2' = tanh(h1_old @ Wx1 + h2_old @ Wh1 + b1) K=1024
        Alo = g_h + (2 + q) * HSZ; Ahi = g_h + (4 + q) * HSZ;
        Blo = Wx1;                 Bhi = Wh1;
        out = g_h + (4 + p) * HSZ; nst = 32;
    }

    __shared__ __align__(16) float As[2][KB][68];    // 17408 B (also epilogue scratch)
    __shared__ __align__(16) float Bs[2][KB][64];    // 16384 B

    int tid  = threadIdx.x;
    int gtid = tid & 127;                            // position inside k-group
    int koff = (tid >> 7) << 4;                      // 0 (warps 0-3) or 16 (warps 4-7)
    int n0 = blockIdx.x * 64;
    int m0 = (blockIdx.y & 3) * 64;
    int tm = gtid >> 3, tn = gtid & 7;

    u64 acc[4][4];
#pragma unroll
    for (int i = 0; i < 4; i++)
#pragma unroll
        for (int j = 0; j < 4; j++) acc[i][j] = 0ull;

    float4 ra[2], rb[2];
    auto ldg = [&](int s) {
        const float* A = (s < 16) ? Alo : Ahi;
        const float* B = (s < 16) ? Blo : Bhi;
        int kc = (s * KB) & 511;
#pragma unroll
        for (int it = 0; it < 2; it++) {
            int idx = tid + it * 256;
            int m  = idx >> 3, kg = idx & 7;         // A: 64 rows x 32 k
            ra[it] = *(const float4*)&A[(size_t)(m0 + m) * UNIT + kc + kg * 4];
            int kk = idx >> 4, ng = idx & 15;        // B: 32 k x 64 n
            rb[it] = *(const float4*)&B[(size_t)(kc + kk) * UNIT + n0 + ng * 4];
        }
    };
    auto sts = [&](int buf) {
#pragma unroll
        for (int it = 0; it < 2; it++) {
            int idx = tid + it * 256;
            int m = idx >> 3, kg = idx & 7;
            As[buf][kg * 4 + 0][m] = ra[it].x; As[buf][kg * 4 + 1][m] = ra[it].y;
            As[buf][kg * 4 + 2][m] = ra[it].z; As[buf][kg * 4 + 3][m] = ra[it].w;
            int kk = idx >> 4, ng = idx & 15;
            *(float4*)&Bs[buf][kk][ng * 4] = rb[it];
        }
    };

    ldg(0); sts(0);
    __syncthreads();
    for (int s = 0; s < nst; s++) {
        int cur = s & 1;
        bool more = (s + 1 < nst);
        if (more) ldg(s + 1);                        // LDG overlaps compute below
#pragma unroll
        for (int k5 = 0; k5 < 16; k5++) {
            int k = koff + k5;
            float4 a = *(const float4*)&As[cur][k][tm * 4];
            const ulonglong2* bp = (const ulonglong2*)&Bs[cur][k][tn * 8];
            ulonglong2 bA = bp[0]; ulonglong2 bB = bp[1];
            u64 aa;
            aa = bcast2(a.x); fma2(acc[0][0],aa,bA.x); fma2(acc[0][1],aa,bA.y);
                              fma2(acc[0][2],aa,bB.x); fma2(acc[0][3],aa,bB.y);
            aa = bcast2(a.y); fma2(acc[1][0],aa,bA.x); fma2(acc[1][1],aa,bA.y);
                              fma2(acc[1][2],aa,bB.x); fma2(acc[1][3],aa,bB.y);
            aa = bcast2(a.z); fma2(acc[2][0],aa,bA.x); fma2(acc[2][1],aa,bA.y);
                              fma2(acc[2][2],aa,bB.x); fma2(acc[2][3],aa,bB.y);
            aa = bcast2(a.w); fma2(acc[3][0],aa,bA.x); fma2(acc[3][1],aa,bA.y);
                              fma2(acc[3][2],aa,bB.x); fma2(acc[3][3],aa,bB.y);
        }
        if (more) {
            sts(cur ^ 1);                            // safe: buf cur^1 idle since s-1 sync
            __syncthreads();
        }
    }

    // Reduce the two K-partials through SMEM (reuse As as scratch: 16KB needed)
    __syncthreads();
    u64* scratch = (u64*)&As[0][0][0];
    if (tid >= 128) {
#pragma unroll
        for (int i = 0; i < 4; i++)
#pragma unroll
            for (int j = 0; j < 4; j++)
                scratch[gtid * 16 + i * 4 + j] = acc[i][j];
    }
    __syncthreads();
    if (tid < 128) {
#pragma unroll
        for (int i = 0; i < 4; i++)
#pragma unroll
            for (int j = 0; j < 4; j++)
                add2(acc[i][j], scratch[gtid * 16 + i * 4 + j]);

        // Epilogue: + (emb2 gather | bias), tanh, coalesced store
#pragma unroll
        for (int i = 0; i < 4; i++) {
            int m = m0 + tm * 4 + i;                 // batch index
            float add[8];
            if (layer == 0) {
                int tok = tokens[m * SEQ + t];
                const float4* e = (const float4*)(g_emb2 + (size_t)tok * UNIT + n0 + tn * 8);
                float4 e0 = e[0], e1 = e[1];
                add[0]=e0.x; add[1]=e0.y; add[2]=e0.z; add[3]=e0.w;
                add[4]=e1.x; add[5]=e1.y; add[6]=e1.z; add[7]=e1.w;
            } else {
                const float4* bb = (const float4*)(b1 + n0 + tn * 8);
                float4 b0v = bb[0], b1v = bb[1];
                add[0]=b0v.x; add[1]=b0v.y; add[2]=b0v.z; add[3]=b0v.w;
                add[4]=b1v.x; add[5]=b1v.y; add[6]=b1v.z; add[7]=b1v.w;
            }
            float o[8];
#pragma unroll
            for (int j = 0; j < 4; j++) {
                float2 v = unpack2(acc[i][j]);
                o[j * 2]     = tanhf(v.x + add[j * 2]);
                o[j * 2 + 1] = tanhf(v.y + add[j * 2 + 1]);
            }
            float4* po = (float4*)(out + (size_t)m * UNIT + n0 + tn * 8);
            po[0] = make_float4(o[0], o[1], o[2], o[3]);
            po[1] = make_float4(o[4], o[5], o[6], o[7]);
        }
    }
}

// ---------------------------------------------------------------------------
// out[b] = sigmoid(h2_final[b] . fc_w + fc_b)   ; h2_final lives at parity 1
// ---------------------------------------------------------------------------
__global__ void final_kernel(const float* __restrict__ fc_w,
                             const float* __restrict__ fc_b,
                             float* __restrict__ out)
{
    int b = blockIdx.x;
    int lane = threadIdx.x;
    const float* h = g_h + 5 * HSZ + (size_t)b * UNIT;  // layer2, parity (513&1)=1
    float s = 0.f;
    for (int k = lane; k < UNIT; k += 32) s += h[k] * fc_w[k];
#pragma unroll
    for (int o = 16; o; o >>= 1) s += __shfl_xor_sync(0xffffffffu, s, o);
    if (lane == 0) out[b] = 1.f / (1.f + expf(-(s + fc_b[0])));
}

// ---------------------------------------------------------------------------
extern "C" void kernel_launch(void* const* d_in, const int* in_sizes, int n_in,
                              void* d_out, int out_size)
{
    const int*   tokens = (const int*)  d_in[0];
    const float* emb    = (const float*)d_in[1];
    const float* Wx0    = (const float*)d_in[2];
    const float* Wh0    = (const float*)d_in[3];
    const float* b0     = (const float*)d_in[4];
    const float* Wx1    = (const float*)d_in[5];
    const float* Wh1    = (const float*)d_in[6];
    const float* b1     = (const float*)d_in[7];
    const float* fc_w   = (const float*)d_in[8];
    const float* fc_b   = (const float*)d_in[9];
    float* out = (float*)d_out;

    // 1. Zero hidden-state buffers (required every launch: graph replays reuse them)
    zero_h_kernel<<<768, 256>>>();

    // 2. emb2 = emb @ Wx0 + b0   (one-shot, fully parallel)
    emb2_kernel<<<dim3(8, (VOCAB + 63) / 64), 128>>>(emb, Wx0, b0);

    // 3. Wavefront over 514 ticks: layer0@t, layer1@t-1, layer2@t-2 per tick
    for (int t = 0; t < SEQ + 2; t++)
        tick_kernel<<<dim3(8, 12), 256>>>(t, Wh0, Wx1, Wh1, b1, tokens);

    // 4. logits -> sigmoid
    final_kernel<<<BATCH, 32>>>(fc_w, fc_b, out);
}

// round 13
// speedup vs baseline: 1.1121x; 1.0011x over previous
#include <cuda_runtime.h>
#include <math.h>

#define BATCH 256
#define SEQ   512
#define VOCAB 50000
#define EMB   128
#define UNIT  512
#define HSZ   (BATCH*UNIT)   // one hidden-state matrix
#define KB    32             // k-rows staged per iteration in tick kernel

// Scratch (static device arrays: allocation-free per harness rules)
__device__ __align__(16) float g_emb2[(size_t)VOCAB * UNIT]; // emb @ Wx0 + b0  (~102 MB)
__device__ __align__(16) float g_h[6 * HSZ];                 // [layer*2 + parity][B][U]

typedef unsigned long long u64;

__device__ __forceinline__ void fma2(u64& d, u64 a, u64 b) {
    asm("fma.rn.f32x2 %0, %1, %2, %0;" : "+l"(d) : "l"(a), "l"(b));
}
__device__ __forceinline__ void add2(u64& d, u64 a) {
    asm("add.rn.f32x2 %0, %0, %1;" : "+l"(d) : "l"(a));
}
__device__ __forceinline__ u64 bcast2(float x) {
    u64 r; asm("mov.b64 %0, {%1, %1};" : "=l"(r) : "f"(x)); return r;
}
__device__ __forceinline__ float2 unpack2(u64 v) {
    float2 r; asm("mov.b64 {%0, %1}, %2;" : "=f"(r.x), "=f"(r.y) : "l"(v)); return r;
}

// ---------------------------------------------------------------------------
// Zero the 6 hidden-state buffers (must be zero at the start of EVERY launch)
// ---------------------------------------------------------------------------
__global__ void zero_h_kernel() {
    int i = blockIdx.x * 256 + threadIdx.x;      // 768*256 float4 = 6*HSZ floats
    ((float4*)g_h)[i] = make_float4(0.f, 0.f, 0.f, 0.f);
}

// ---------------------------------------------------------------------------
// emb2[v][n] = sum_k emb[v][k] * Wx0[k][n] + b0[n]     (M=50000, N=512, K=128)
// (one-shot, fully parallel, ~2% of runtime)
// ---------------------------------------------------------------------------
__global__ __launch_bounds__(128) void emb2_kernel(
    const float* __restrict__ emb, const float* __restrict__ Wx0,
    const float* __restrict__ b0)
{
    __shared__ __align__(16) float As[16][68];
    __shared__ __align__(16) float Bs[16][64];
    int tid = threadIdx.x;
    int n0 = blockIdx.x * 64;
    int m0 = blockIdx.y * 64;
    int tm = tid >> 3, tn = tid & 7;

    u64 acc[4][4];
#pragma unroll
    for (int i = 0; i < 4; i++)
#pragma unroll
        for (int j = 0; j < 4; j++) acc[i][j] = 0ull;

    float4 ra[2], rb[2];
    auto ld = [&](int kb) {
#pragma unroll
        for (int it = 0; it < 2; it++) {
            int idx = tid + it * 128;
            int m = idx >> 2, kg = idx & 3;
            int row = m0 + m;
            if (row < VOCAB)
                ra[it] = *(const float4*)&emb[(size_t)row * EMB + kb * 16 + kg * 4];
            else
                ra[it] = make_float4(0.f, 0.f, 0.f, 0.f);
            int kk = idx >> 4, ng = idx & 15;
            rb[it] = *(const float4*)&Wx0[(size_t)(kb * 16 + kk) * UNIT + n0 + ng * 4];
        }
    };

    ld(0);
    for (int kb = 0; kb < 8; kb++) {                 // K = 128 = 8 * 16
#pragma unroll
        for (int it = 0; it < 2; it++) {
            int idx = tid + it * 128;
            int m = idx >> 2, kg = idx & 3;
            As[kg * 4 + 0][m] = ra[it].x; As[kg * 4 + 1][m] = ra[it].y;
            As[kg * 4 + 2][m] = ra[it].z; As[kg * 4 + 3][m] = ra[it].w;
            int kk = idx >> 4, ng = idx & 15;
            *(float4*)&Bs[kk][ng * 4] = rb[it];
        }
        __syncthreads();
        if (kb + 1 < 8) ld(kb + 1);
#pragma unroll
        for (int k5 = 0; k5 < 16; k5++) {
            float4 a = *(const float4*)&As[k5][tm * 4];
            const ulonglong2* bp = (const ulonglong2*)&Bs[k5][tn * 8];
            ulonglong2 bA = bp[0]; ulonglong2 bB = bp[1];
            u64 aa;
            aa = bcast2(a.x); fma2(acc[0][0],aa,bA.x); fma2(acc[0][1],aa,bA.y);
                              fma2(acc[0][2],aa,bB.x); fma2(acc[0][3],aa,bB.y);
            aa = bcast2(a.y); fma2(acc[1][0],aa,bA.x); fma2(acc[1][1],aa,bA.y);
                              fma2(acc[1][2],aa,bB.x); fma2(acc[1][3],aa,bB.y);
            aa = bcast2(a.z); fma2(acc[2][0],aa,bA.x); fma2(acc[2][1],aa,bA.y);
                              fma2(acc[2][2],aa,bB.x); fma2(acc[2][3],aa,bB.y);
            aa = bcast2(a.w); fma2(acc[3][0],aa,bA.x); fma2(acc[3][1],aa,bA.y);
                              fma2(acc[3][2],aa,bB.x); fma2(acc[3][3],aa,bB.y);
        }
        __syncthreads();
    }

#pragma unroll
    for (int i = 0; i < 4; i++) {
        int row = m0 + tm * 4 + i;
        if (row >= VOCAB) break;
        float* po = g_emb2 + (size_t)row * UNIT + n0 + tn * 8;
        const float* bb = b0 + n0 + tn * 8;
#pragma unroll
        for (int j = 0; j < 4; j++) {
            float2 v = unpack2(acc[i][j]);
            ((float2*)po)[j] = make_float2(v.x + bb[j * 2], v.y + bb[j * 2 + 1]);
        }
    }
}

// ---------------------------------------------------------------------------
// One wavefront tick: layer0@t, layer1@t-1, layer2@t-2 fused GEMM + tanh.
// v3: 512 threads, 4-way in-block K-split (4 warps/SMSP for latency hiding),
//     double-buffered 32-k SMEM stages, 2-sync tree reduction of the four
//     K-partials through dedicated SMEM scratch, then tanh epilogue (group 0).
// Grid (8, 12): blockIdx.y/4 = layer, (blockIdx.y&3)*64 = batch-tile origin.
// ---------------------------------------------------------------------------
__global__ __launch_bounds__(512) void tick_kernel(
    int t,
    const float* __restrict__ Wh0, const float* __restrict__ Wx1,
    const float* __restrict__ Wh1, const float* __restrict__ b1,
    const int* __restrict__ tokens)
{
    int layer = blockIdx.y >> 2;
    if (layer == 0 && t >= SEQ) return;              // h0(t) only for t in [0,512)
    if (layer == 1 && (t < 1 || t > SEQ)) return;    // h1(t-1) for t in [1,512]
    if (layer == 2 && t < 2) return;                 // h2(t-2) for t in [2,513]

    int p = t & 1, q = p ^ 1;
    const float *Alo, *Ahi, *Blo, *Bhi;
    float* out;
    int nst;                                         // number of 32-k stages
    if (layer == 0) {        // h0' = tanh(h0_old @ Wh0 + emb2[tok])         K=512
        Alo = g_h + q * HSZ;       Ahi = Alo;
        Blo = Wh0;                 Bhi = Wh0;
        out = g_h + p * HSZ;       nst = 16;
    } else if (layer == 1) { // h1' = tanh(h0_old @ Wx1 + h1_old @ Wh1 + b1) K=1024
        Alo = g_h + q * HSZ;       Ahi = g_h + (2 + q) * HSZ;
        Blo = Wx1;                 Bhi = Wh1;
        out = g_h + (2 + p) * HSZ; nst = 32;
    } else {                 // h2' = tanh(h1_old @ Wx1 + h2_old @ Wh1 + b1) K=1024
        Alo = g_h + (2 + q) * HSZ; Ahi = g_h + (4 + q) * HSZ;
        Blo = Wx1;                 Bhi = Wh1;
        out = g_h + (4 + p) * HSZ; nst = 32;
    }

    __shared__ __align__(16) float As[2][KB][68];    // 17408 B
    __shared__ __align__(16) float Bs[2][KB][64];    // 16384 B
    __shared__ __align__(16) u64 red[2][128][17];    // 34816 B reduction scratch

    int tid  = threadIdx.x;
    int grp  = tid >> 7;                             // K-split group 0..3
    int gtid = tid & 127;                            // position inside group
    int koff = grp * 8;                              // this group's k-offset in stage
    int n0 = blockIdx.x * 64;
    int m0 = (blockIdx.y & 3) * 64;
    int tm = gtid >> 3, tn = gtid & 7;

    u64 acc[4][4];
#pragma unroll
    for (int i = 0; i < 4; i++)
#pragma unroll
        for (int j = 0; j < 4; j++) acc[i][j] = 0ull;

    // Loader: 512 threads, one float4 of A and one of B each per stage.
    float4 ra, rb;
    int lm = tid >> 3, lkg = tid & 7;                // A: 64 rows x 32 k
    int lkk = tid >> 4, lng = tid & 15;              // B: 32 k  x 64 n
    auto ldg = [&](int s) {
        const float* A = (s < 16) ? Alo : Ahi;
        const float* B = (s < 16) ? Blo : Bhi;
        int kc = (s * KB) & 511;
        ra = *(const float4*)&A[(size_t)(m0 + lm) * UNIT + kc + lkg * 4];
        rb = *(const float4*)&B[(size_t)(kc + lkk) * UNIT + n0 + lng * 4];
    };
    auto sts = [&](int buf) {
        As[buf][lkg * 4 + 0][lm] = ra.x; As[buf][lkg * 4 + 1][lm] = ra.y;
        As[buf][lkg * 4 + 2][lm] = ra.z; As[buf][lkg * 4 + 3][lm] = ra.w;
        *(float4*)&Bs[buf][lkk][lng * 4] = rb;
    };

    ldg(0); sts(0);
    __syncthreads();
    for (int s = 0; s < nst; s++) {
        int cur = s & 1;
        bool more = (s + 1 < nst);
        if (more) ldg(s + 1);                        // LDG overlaps compute below
#pragma unroll
        for (int k5 = 0; k5 < 8; k5++) {
            int k = koff + k5;
            float4 a = *(const float4*)&As[cur][k][tm * 4];
            const ulonglong2* bp = (const ulonglong2*)&Bs[cur][k][tn * 8];
            ulonglong2 bA = bp[0]; ulonglong2 bB = bp[1];
            u64 aa;
            aa = bcast2(a.x); fma2(acc[0][0],aa,bA.x); fma2(acc[0][1],aa,bA.y);
                              fma2(acc[0][2],aa,bB.x); fma2(acc[0][3],aa,bB.y);
            aa = bcast2(a.y); fma2(acc[1][0],aa,bA.x); fma2(acc[1][1],aa,bA.y);
                              fma2(acc[1][2],aa,bB.x); fma2(acc[1][3],aa,bB.y);
            aa = bcast2(a.z); fma2(acc[2][0],aa,bA.x); fma2(acc[2][1],aa,bA.y);
                              fma2(acc[2][2],aa,bB.x); fma2(acc[2][3],aa,bB.y);
            aa = bcast2(a.w); fma2(acc[3][0],aa,bA.x); fma2(acc[3][1],aa,bA.y);
                              fma2(acc[3][2],aa,bB.x); fma2(acc[3][3],aa,bB.y);
        }
        if (more) {
            sts(cur ^ 1);                            // buf cur^1 idle since s-1 sync
            __syncthreads();
        }
    }

    // Tree-reduce the four K-partials: (g2->red0, g3->red1); (g0+=red0, g1+=red1,
    // g1->red0); (g0+=red0). Two syncs.
    if (grp == 2) {
#pragma unroll
        for (int i = 0; i < 4; i++)
#pragma unroll
            for (int j = 0; j < 4; j++) red[0][gtid][i * 4 + j] = acc[i][j];
    } else if (grp == 3) {
#pragma unroll
        for (int i = 0; i < 4; i++)
#pragma unroll
            for (int j = 0; j < 4; j++) red[1][gtid][i * 4 + j] = acc[i][j];
    }
    __syncthreads();
    if (grp == 0) {
#pragma unroll
        for (int i = 0; i < 4; i++)
#pragma unroll
            for (int j = 0; j < 4; j++) add2(acc[i][j], red[0][gtid][i * 4 + j]);
    } else if (grp == 1) {
#pragma unroll
        for (int i = 0; i < 4; i++)
#pragma unroll
            for (int j = 0; j < 4; j++) {
                add2(acc[i][j], red[1][gtid][i * 4 + j]);
                red[0][gtid][i * 4 + j] = acc[i][j];
            }
    }
    __syncthreads();
    if (grp == 0) {
#pragma unroll
        for (int i = 0; i < 4; i++)
#pragma unroll
            for (int j = 0; j < 4; j++) add2(acc[i][j], red[0][gtid][i * 4 + j]);

        // Epilogue: + (emb2 gather | bias), tanh, coalesced store
#pragma unroll
        for (int i = 0; i < 4; i++) {
            int m = m0 + tm * 4 + i;                 // batch index
            float add[8];
            if (layer == 0) {
                int tok = tokens[m * SEQ + t];
                const float4* e = (const float4*)(g_emb2 + (size_t)tok * UNIT + n0 + tn * 8);
                float4 e0 = e[0], e1 = e[1];
                add[0]=e0.x; add[1]=e0.y; add[2]=e0.z; add[3]=e0.w;
                add[4]=e1.x; add[5]=e1.y; add[6]=e1.z; add[7]=e1.w;
            } else {
                const float4* bb = (const float4*)(b1 + n0 + tn * 8);
                float4 b0v = bb[0], b1v = bb[1];
                add[0]=b0v.x; add[1]=b0v.y; add[2]=b0v.z; add[3]=b0v.w;
                add[4]=b1v.x; add[5]=b1v.y; add[6]=b1v.z; add[7]=b1v.w;
            }
            float o[8];
#pragma unroll
            for (int j = 0; j < 4; j++) {
                float2 v = unpack2(acc[i][j]);
                o[j * 2]     = tanhf(v.x + add[j * 2]);
                o[j * 2 + 1] = tanhf(v.y + add[j * 2 + 1]);
            }
            float4* po = (float4*)(out + (size_t)m * UNIT + n0 + tn * 8);
            po[0] = make_float4(o[0], o[1], o[2], o[3]);
            po[1] = make_float4(o[4], o[5], o[6], o[7]);
        }
    }
}

// ---------------------------------------------------------------------------
// out[b] = sigmoid(h2_final[b] . fc_w + fc_b)   ; h2_final lives at parity 1
// ---------------------------------------------------------------------------
__global__ void final_kernel(const float* __restrict__ fc_w,
                             const float* __restrict__ fc_b,
                             float* __restrict__ out)
{
    int b = blockIdx.x;
    int lane = threadIdx.x;
    const float* h = g_h + 5 * HSZ + (size_t)b * UNIT;  // layer2, parity (513&1)=1
    float s = 0.f;
    for (int k = lane; k < UNIT; k += 32) s += h[k] * fc_w[k];
#pragma unroll
    for (int o = 16; o; o >>= 1) s += __shfl_xor_sync(0xffffffffu, s, o);
    if (lane == 0) out[b] = 1.f / (1.f + expf(-(s + fc_b[0])));
}

// ---------------------------------------------------------------------------
extern "C" void kernel_launch(void* const* d_in, const int* in_sizes, int n_in,
                              void* d_out, int out_size)
{
    const int*   tokens = (const int*)  d_in[0];
    const float* emb    = (const float*)d_in[1];
    const float* Wx0    = (const float*)d_in[2];
    const float* Wh0    = (const float*)d_in[3];
    const float* b0     = (const float*)d_in[4];
    const float* Wx1    = (const float*)d_in[5];
    const float* Wh1    = (const float*)d_in[6];
    const float* b1     = (const float*)d_in[7];
    const float* fc_w   = (const float*)d_in[8];
    const float* fc_b   = (const float*)d_in[9];
    float* out = (float*)d_out;

    // 1. Zero hidden-state buffers (required every launch: graph replays reuse them)
    zero_h_kernel<<<768, 256>>>();

    // 2. emb2 = emb @ Wx0 + b0   (one-shot, fully parallel)
    emb2_kernel<<<dim3(8, (VOCAB + 63) / 64), 128>>>(emb, Wx0, b0);

    // 3. Wavefront over 514 ticks: layer0@t, layer1@t-1, layer2@t-2 per tick
    for (int t = 0; t < SEQ + 2; t++)
        tick_kernel<<<dim3(8, 12), 512>>>(t, Wh0, Wx1, Wh1, b1, tokens);

    // 4. logits -> sigmoid
    final_kernel<<<BATCH, 32>>>(fc_w, fc_b, out);
}

// round 17
// speedup vs baseline: 3.1375x; 2.8212x over previous
#include <cuda_runtime.h>
#include <cuda_bf16.h>
#include <math.h>
#include <stdint.h>

#define BATCH 256
#define SEQ   512
#define VOCAB 50000
#define EMB   128
#define UNIT  512
#define HSZ   (BATCH*UNIT)

// tick GEMM tiling: block C tile 64x64, 4 warps (32x32 each), K chunk = 32.
// SMEM rows are 128B: [32k of hi | 32k of lo] bf16, SW128-swizzled.
#define KCH   32
#define A_OFF 0
#define B_OFF 8192
#define STAGE 16384                    // A(8KB) + B(8KB)
#define SW128(o) ((o) ^ (((o) >> 3) & 0x70))

// ---- device scratch (static: allocation-free) ----
__device__ __align__(16) float g_emb2[(size_t)VOCAB * UNIT];    // emb@Wx0+b0
__device__ __align__(16) float g_h[6 * HSZ];                    // fp32 h (epilogue/final)
__device__ __align__(16) __nv_bfloat16 g_hh[6 * HSZ];           // h hi
__device__ __align__(16) __nv_bfloat16 g_hl[6 * HSZ];           // h lo
__device__ __align__(16) __nv_bfloat16 g_wt0h[UNIT * UNIT];     // Wh0^T hi [n][k]
__device__ __align__(16) __nv_bfloat16 g_wt0l[UNIT * UNIT];
__device__ __align__(16) __nv_bfloat16 g_wt1h[UNIT * 2 * UNIT]; // [Wx1;Wh1]^T hi [n][k]
__device__ __align__(16) __nv_bfloat16 g_wt1l[UNIT * 2 * UNIT];

typedef unsigned long long u64;

// ---- PTX helpers ----
__device__ __forceinline__ uint32_t smem_u32(const void* p) {
    uint32_t a;
    asm("{ .reg .u64 t; cvta.to.shared.u64 t, %1; cvt.u32.u64 %0, t; }" : "=r"(a) : "l"(p));
    return a;
}
__device__ __forceinline__ void cp16(uint32_t dst, const void* src) {
    asm volatile("cp.async.cg.shared.global [%0], [%1], 16;" :: "r"(dst), "l"(src));
}
__device__ __forceinline__ void cp_commit() {
    asm volatile("cp.async.commit_group;" ::: "memory");
}
template<int N> __device__ __forceinline__ void cp_wait() {
    asm volatile("cp.async.wait_group %0;" :: "n"(N) : "memory");
}
__device__ __forceinline__ void ldm4(uint32_t* r, uint32_t addr) {
    asm volatile("ldmatrix.sync.aligned.m8n8.x4.shared.b16 {%0,%1,%2,%3}, [%4];"
                 : "=r"(r[0]), "=r"(r[1]), "=r"(r[2]), "=r"(r[3]) : "r"(addr));
}
__device__ __forceinline__ void mma16816(float* d, const uint32_t* a, uint32_t b0, uint32_t b1) {
    asm volatile("mma.sync.aligned.m16n8k16.row.col.f32.bf16.bf16.f32 "
                 "{%0,%1,%2,%3}, {%4,%5,%6,%7}, {%8,%9}, {%0,%1,%2,%3};"
                 : "+f"(d[0]), "+f"(d[1]), "+f"(d[2]), "+f"(d[3])
                 : "r"(a[0]), "r"(a[1]), "r"(a[2]), "r"(a[3]), "r"(b0), "r"(b1));
}

// f32x2 helpers for the fp32 emb2 GEMM
__device__ __forceinline__ void fma2(u64& d, u64 a, u64 b) {
    asm("fma.rn.f32x2 %0, %1, %2, %0;" : "+l"(d) : "l"(a), "l"(b));
}
__device__ __forceinline__ u64 bcast2(float x) {
    u64 r; asm("mov.b64 %0, {%1, %1};" : "=l"(r) : "f"(x)); return r;
}
__device__ __forceinline__ float2 unpack2(u64 v) {
    float2 r; asm("mov.b64 {%0, %1}, %2;" : "=f"(r.x), "=f"(r.y) : "l"(v)); return r;
}

// ---------------------------------------------------------------------------
// Zero h buffers (fp32 + bf16 hi/lo)
// ---------------------------------------------------------------------------
__global__ void zero_h_kernel() {
    int i = blockIdx.x * 256 + threadIdx.x;
    if (i < 196608)        ((float4*)g_h)[i] = make_float4(0.f, 0.f, 0.f, 0.f);
    else if (i < 294912)   ((uint4*)g_hh)[i - 196608] = make_uint4(0, 0, 0, 0);
    else                   ((uint4*)g_hl)[i - 294912] = make_uint4(0, 0, 0, 0);
}

// ---------------------------------------------------------------------------
// Weight prep: transpose + split into bf16 hi/lo.
// wt0[n][k] = Wh0[k][n];  wt1[n][k] = (k<512 ? Wx1[k][n] : Wh1[k-512][n]).
// ---------------------------------------------------------------------------
__global__ void wprep_kernel(const float* __restrict__ Wh0,
                             const float* __restrict__ Wx1,
                             const float* __restrict__ Wh1)
{
    int i = blockIdx.x * 256 + threadIdx.x;
    float v; __nv_bfloat16 *dh, *dl; int di;
    if (i < UNIT * UNIT) {
        int n = i >> 9, k = i & 511;
        v = Wh0[k * UNIT + n]; dh = g_wt0h; dl = g_wt0l; di = n * UNIT + k;
    } else {
        int j = i - UNIT * UNIT;
        int n = j >> 10, k = j & 1023;
        v = (k < UNIT) ? Wx1[k * UNIT + n] : Wh1[(k - UNIT) * UNIT + n];
        dh = g_wt1h; dl = g_wt1l; di = n * 2 * UNIT + k;
    }
    __nv_bfloat16 h = __float2bfloat16(v);
    dh[di] = h;
    dl[di] = __float2bfloat16(v - __bfloat162float(h));
}

// ---------------------------------------------------------------------------
// emb2[v][n] = sum_k emb[v][k]*Wx0[k][n] + b0[n]   (fp32, one-shot)
// ---------------------------------------------------------------------------
__global__ __launch_bounds__(128) void emb2_kernel(
    const float* __restrict__ emb, const float* __restrict__ Wx0,
    const float* __restrict__ b0)
{
    __shared__ __align__(16) float As[16][68];
    __shared__ __align__(16) float Bs[16][64];
    int tid = threadIdx.x;
    int n0 = blockIdx.x * 64;
    int m0 = blockIdx.y * 64;
    int tm = tid >> 3, tn = tid & 7;

    u64 acc[4][4];
#pragma unroll
    for (int i = 0; i < 4; i++)
#pragma unroll
        for (int j = 0; j < 4; j++) acc[i][j] = 0ull;

    float4 ra[2], rb[2];
    auto ld = [&](int kb) {
#pragma unroll
        for (int it = 0; it < 2; it++) {
            int idx = tid + it * 128;
            int m = idx >> 2, kg = idx & 3;
            int row = m0 + m;
            if (row < VOCAB)
                ra[it] = *(const float4*)&emb[(size_t)row * EMB + kb * 16 + kg * 4];
            else
                ra[it] = make_float4(0.f, 0.f, 0.f, 0.f);
            int kk = idx >> 4, ng = idx & 15;
            rb[it] = *(const float4*)&Wx0[(size_t)(kb * 16 + kk) * UNIT + n0 + ng * 4];
        }
    };

    ld(0);
    for (int kb = 0; kb < 8; kb++) {
#pragma unroll
        for (int it = 0; it < 2; it++) {
            int idx = tid + it * 128;
            int m = idx >> 2, kg = idx & 3;
            As[kg * 4 + 0][m] = ra[it].x; As[kg * 4 + 1][m] = ra[it].y;
            As[kg * 4 + 2][m] = ra[it].z; As[kg * 4 + 3][m] = ra[it].w;
            int kk = idx >> 4, ng = idx & 15;
            *(float4*)&Bs[kk][ng * 4] = rb[it];
        }
        __syncthreads();
        if (kb + 1 < 8) ld(kb + 1);
#pragma unroll
        for (int k5 = 0; k5 < 16; k5++) {
            float4 a = *(const float4*)&As[k5][tm * 4];
            const ulonglong2* bp = (const ulonglong2*)&Bs[k5][tn * 8];
            ulonglong2 bA = bp[0]; ulonglong2 bB = bp[1];
            u64 aa;
            aa = bcast2(a.x); fma2(acc[0][0],aa,bA.x); fma2(acc[0][1],aa,bA.y);
                              fma2(acc[0][2],aa,bB.x); fma2(acc[0][3],aa,bB.y);
            aa = bcast2(a.y); fma2(acc[1][0],aa,bA.x); fma2(acc[1][1],aa,bA.y);
                              fma2(acc[1][2],aa,bB.x); fma2(acc[1][3],aa,bB.y);
            aa = bcast2(a.z); fma2(acc[2][0],aa,bA.x); fma2(acc[2][1],aa,bA.y);
                              fma2(acc[2][2],aa,bB.x); fma2(acc[2][3],aa,bB.y);
            aa = bcast2(a.w); fma2(acc[3][0],aa,bA.x); fma2(acc[3][1],aa,bA.y);
                              fma2(acc[3][2],aa,bB.x); fma2(acc[3][3],aa,bB.y);
        }
        __syncthreads();
    }

#pragma unroll
    for (int i = 0; i < 4; i++) {
        int row = m0 + tm * 4 + i;
        if (row >= VOCAB) break;
        float* po = g_emb2 + (size_t)row * UNIT + n0 + tn * 8;
        const float* bb = b0 + n0 + tn * 8;
#pragma unroll
        for (int j = 0; j < 4; j++) {
            float2 v = unpack2(acc[i][j]);
            ((float2*)po)[j] = make_float2(v.x + bb[j * 2], v.y + bb[j * 2 + 1]);
        }
    }
}

// ---------------------------------------------------------------------------
// Wavefront tick on mma.sync (HMMA bf16, fp32 acc), split-bf16:
//   D += Ah*Bh + Ah*Bl + Al*Bh
// Grid (8, 12): x = n-tile; y: layer = y>>2, m0 = (y&3)*64. 128 threads.
// ---------------------------------------------------------------------------
__global__ __launch_bounds__(128) void tick_kernel(
    int t, const int* __restrict__ tokens, const float* __restrict__ b1)
{
    int layer = blockIdx.y >> 2;
    if (layer == 0 && t >= SEQ) return;
    if (layer == 1 && (t < 1 || t > SEQ)) return;
    if (layer == 2 && t < 2) return;

    int p = t & 1, q = p ^ 1;
    const __nv_bfloat16 *Ah0, *Al0, *Ah1, *Al1, *Wh, *Wl;
    int wstride, nst, obuf;
    if (layer == 0) {
        Ah0 = g_hh + (size_t)q * HSZ; Al0 = g_hl + (size_t)q * HSZ;
        Ah1 = Ah0; Al1 = Al0;
        Wh = g_wt0h; Wl = g_wt0l; wstride = UNIT; nst = 16; obuf = p;
    } else if (layer == 1) {
        Ah0 = g_hh + (size_t)q * HSZ;       Al0 = g_hl + (size_t)q * HSZ;
        Ah1 = g_hh + (size_t)(2 + q) * HSZ; Al1 = g_hl + (size_t)(2 + q) * HSZ;
        Wh = g_wt1h; Wl = g_wt1l; wstride = 2 * UNIT; nst = 32; obuf = 2 + p;
    } else {
        Ah0 = g_hh + (size_t)(2 + q) * HSZ; Al0 = g_hl + (size_t)(2 + q) * HSZ;
        Ah1 = g_hh + (size_t)(4 + q) * HSZ; Al1 = g_hl + (size_t)(4 + q) * HSZ;
        Wh = g_wt1h; Wl = g_wt1l; wstride = 2 * UNIT; nst = 32; obuf = 4 + p;
    }

    __shared__ __align__(128) char smem[2 * STAGE];   // 32KB static
    uint32_t sb = smem_u32(smem);
    int tid = threadIdx.x, wid = tid >> 5, lane = tid & 31;
    int warp_m = wid >> 1, warp_n = wid & 1;
    int n0 = blockIdx.x * 64;
    int m0 = (blockIdx.y & 3) * 64;

    float acc[2][4][4];
#pragma unroll
    for (int mi = 0; mi < 2; mi++)
#pragma unroll
        for (int nb = 0; nb < 4; nb++)
#pragma unroll
            for (int e = 0; e < 4; e++) acc[mi][nb][e] = 0.f;

    // ---- cp.async stage loader: rows = 128B [32k hi | 32k lo], SW128 ----
    auto issue = [&](int c) {
        const __nv_bfloat16* ah = (layer == 0 || c < 16) ? Ah0 : Ah1;
        const __nv_bfloat16* al = (layer == 0 || c < 16) ? Al0 : Al1;
        int acol = (layer == 0) ? c * KCH : (c & 15) * KCH;
        int wcol = c * KCH;
        uint32_t base = sb + (uint32_t)(c & 1) * STAGE;
#pragma unroll
        for (int r = 0; r < 4; r++) {
            int idx = tid + r * 128;
            int row = idx >> 3, seg = idx & 7;        // seg 0-3 hi, 4-7 lo
            uint32_t doff = SW128((uint32_t)(row * 128 + seg * 16));
            const __nv_bfloat16* asrc = (seg < 4) ? ah : al;
            cp16(base + A_OFF + doff,
                 asrc + (size_t)(m0 + row) * UNIT + acol + (seg & 3) * 8);
            const __nv_bfloat16* bsrc = (seg < 4) ? Wh : Wl;
            cp16(base + B_OFF + doff,
                 bsrc + (size_t)(n0 + row) * wstride + wcol + (seg & 3) * 8);
        }
    };

    // ---- ldmatrix address lanes ----
    int lr = lane & 7, sel = lane >> 3;
    // A: tiles (m+0,k0)(m+8,k0)(m+0,k8)(m+8,k8); byte = lvl*64 + kk*32 + (sel>>1)*16
    int a_row_base = warp_m * 32 + (sel & 1) * 8 + lr;
    int a_kb = (sel >> 1) * 16;
    // B: tiles nb0..3; byte = lvl*64 + kk*32 + koff(0|16)
    int b_row = warp_n * 32 + sel * 8 + lr;

    issue(0); cp_commit();
    for (int s = 0; s < nst; s++) {
        if (s + 1 < nst) { issue(s + 1); cp_commit(); cp_wait<1>(); }
        else cp_wait<0>();
        __syncthreads();
        uint32_t ab = sb + (uint32_t)(s & 1) * STAGE + A_OFF;
        uint32_t bb = sb + (uint32_t)(s & 1) * STAGE + B_OFF;
#pragma unroll
        for (int kk = 0; kk < 2; kk++) {
            uint32_t ah0[4], ah1[4], al0[4], al1[4];
            uint32_t bh0[4], bh1[4], bl0[4], bl1[4];
            {
                uint32_t r0 = (uint32_t)((a_row_base) * 128 + 0  + kk * 32 + a_kb);
                uint32_t r1 = (uint32_t)((a_row_base + 16) * 128 + 0 + kk * 32 + a_kb);
                ldm4(ah0, ab + SW128(r0));
                ldm4(ah1, ab + SW128(r1));
                ldm4(al0, ab + SW128(r0 + 64));
                ldm4(al1, ab + SW128(r1 + 64));
            }
            {
                uint32_t r0 = (uint32_t)(b_row * 128 + kk * 32);
                ldm4(bh0, bb + SW128(r0));
                ldm4(bh1, bb + SW128(r0 + 16));
                ldm4(bl0, bb + SW128(r0 + 64));
                ldm4(bl1, bb + SW128(r0 + 80));
            }
#pragma unroll
            for (int nb = 0; nb < 4; nb++) {
                mma16816(acc[0][nb], ah0, bh0[nb], bh1[nb]);
                mma16816(acc[1][nb], ah1, bh0[nb], bh1[nb]);
            }
#pragma unroll
            for (int nb = 0; nb < 4; nb++) {
                mma16816(acc[0][nb], ah0, bl0[nb], bl1[nb]);
                mma16816(acc[1][nb], ah1, bl0[nb], bl1[nb]);
            }
#pragma unroll
            for (int nb = 0; nb < 4; nb++) {
                mma16816(acc[0][nb], al0, bh0[nb], bh1[nb]);
                mma16816(acc[1][nb], al1, bh0[nb], bh1[nb]);
            }
        }
        __syncthreads();
    }

    // ---- epilogue: + (emb2 | bias), tanh, store fp32 + bf16 hi/lo ----
    int g = lane >> 2, c2 = (lane & 3) * 2;
#pragma unroll
    for (int mi = 0; mi < 2; mi++) {
        int r0 = m0 + warp_m * 32 + mi * 16 + g;
        int r1 = r0 + 8;
        const float *as0, *as1;
        if (layer == 0) {
            as0 = g_emb2 + (size_t)tokens[r0 * SEQ + t] * UNIT;
            as1 = g_emb2 + (size_t)tokens[r1 * SEQ + t] * UNIT;
        } else { as0 = b1; as1 = b1; }
#pragma unroll
        for (int nb = 0; nb < 4; nb++) {
            int n = n0 + warp_n * 32 + nb * 8 + c2;
            float* a = acc[mi][nb];
            float x0 = tanhf(a[0] + as0[n]), x1 = tanhf(a[1] + as0[n + 1]);
            float y0 = tanhf(a[2] + as1[n]), y1 = tanhf(a[3] + as1[n + 1]);
            size_t o0 = (size_t)obuf * HSZ + (size_t)r0 * UNIT + n;
            size_t o1 = (size_t)obuf * HSZ + (size_t)r1 * UNIT + n;
            *(float2*)(g_h + o0) = make_float2(x0, x1);
            *(float2*)(g_h + o1) = make_float2(y0, y1);
            __nv_bfloat16 hx0 = __float2bfloat16(x0), hx1 = __float2bfloat16(x1);
            __nv_bfloat16 hy0 = __float2bfloat16(y0), hy1 = __float2bfloat16(y1);
            __nv_bfloat162 v;
            v.x = hx0; v.y = hx1; *(__nv_bfloat162*)(g_hh + o0) = v;
            v.x = hy0; v.y = hy1; *(__nv_bfloat162*)(g_hh + o1) = v;
            v.x = __float2bfloat16(x0 - __bfloat162float(hx0));
            v.y = __float2bfloat16(x1 - __bfloat162float(hx1));
            *(__nv_bfloat162*)(g_hl + o0) = v;
            v.x = __float2bfloat16(y0 - __bfloat162float(hy0));
            v.y = __float2bfloat16(y1 - __bfloat162float(hy1));
            *(__nv_bfloat162*)(g_hl + o1) = v;
        }
    }
}

// ---------------------------------------------------------------------------
// out[b] = sigmoid(h2_final . fc_w + fc_b); h2(511) lives at buffer 5
// ---------------------------------------------------------------------------
__global__ void final_kernel(const float* __restrict__ fc_w,
                             const float* __restrict__ fc_b,
                             float* __restrict__ out)
{
    int b = blockIdx.x;
    int lane = threadIdx.x;
    const float* h = g_h + 5 * (size_t)HSZ + (size_t)b * UNIT;
    float s = 0.f;
    for (int k = lane; k < UNIT; k += 32) s += h[k] * fc_w[k];
#pragma unroll
    for (int o = 16; o; o >>= 1) s += __shfl_xor_sync(0xffffffffu, s, o);
    if (lane == 0) out[b] = 1.f / (1.f + expf(-(s + fc_b[0])));
}

// ---------------------------------------------------------------------------
extern "C" void kernel_launch(void* const* d_in, const int* in_sizes, int n_in,
                              void* d_out, int out_size)
{
    const int*   tokens = (const int*)  d_in[0];
    const float* emb    = (const float*)d_in[1];
    const float* Wx0    = (const float*)d_in[2];
    const float* Wh0    = (const float*)d_in[3];
    const float* b0     = (const float*)d_in[4];
    const float* Wx1    = (const float*)d_in[5];
    const float* Wh1    = (const float*)d_in[6];
    const float* b1     = (const float*)d_in[7];
    const float* fc_w   = (const float*)d_in[8];
    const float* fc_b   = (const float*)d_in[9];
    float* out = (float*)d_out;

    zero_h_kernel<<<1536, 256>>>();
    wprep_kernel<<<3072, 256>>>(Wh0, Wx1, Wh1);
    emb2_kernel<<<dim3(8, (VOCAB + 63) / 64), 128>>>(emb, Wx0, b0);

    for (int t = 0; t < SEQ + 2; t++)
        tick_kernel<<<dim3(8, 12), 128>>>(t, tokens, b1);

    final_kernel<<<BATCH, 32>>>(fc_w, fc_b, out);
}